// round 2
// baseline (speedup 1.0000x reference)
#include <cuda_runtime.h>
#include <math.h>

// BoundaryLoss collapses analytically:
//   dist_map = min(dist_to_zero_set, dist_to_nonzero_set) == 0 everywhere
//   => w = 1, max(w) = 1, final_weight = 1 + THETA = 6 (constant)
//   => out = 6 * mean( softplus(pred) - pred*target ),  N = 524288
//
// Single fused kernel: block partials + threadfence last-block final reduce.
// Deterministic: the atomic only selects WHICH block finalizes; the final
// summation reads a fixed array in a fixed order.

#define N_ELEMS   524288
#define BLOCKS    512
#define THREADS   256                // BLOCKS*THREADS*4 == N_ELEMS exactly

__device__ float        g_partials[BLOCKS];
__device__ unsigned int g_count = 0;   // reset by the finalizing block each call

__device__ __forceinline__ float softplus_f(float x) {
    // logaddexp(0, x) = max(x,0) + log1p(exp(-|x|))
    return fmaxf(x, 0.0f) + log1pf(__expf(-fabsf(x)));
}

__device__ __forceinline__ float block_reduce_256(float s, float* warp_sums) {
    #pragma unroll
    for (int off = 16; off > 0; off >>= 1)
        s += __shfl_down_sync(0xFFFFFFFFu, s, off);
    const int lane = threadIdx.x & 31;
    const int wid  = threadIdx.x >> 5;
    if (lane == 0) warp_sums[wid] = s;
    __syncthreads();
    float v = 0.0f;
    if (wid == 0) {
        v = (lane < THREADS / 32) ? warp_sums[lane] : 0.0f;
        #pragma unroll
        for (int off = 4; off > 0; off >>= 1)
            v += __shfl_down_sync(0xFFFFFFFFu, v, off);
    }
    return v;   // valid in lane 0 of warp 0
}

__global__ __launch_bounds__(THREADS) void bce_fused_kernel(
    const float* __restrict__ pred, const float* __restrict__ target,
    float* __restrict__ out)
{
    __shared__ float warp_sums[THREADS / 32];
    __shared__ bool  is_last;

    const int gid = blockIdx.x * THREADS + threadIdx.x;  // one float4 per thread

    const float4 p = reinterpret_cast<const float4*>(pred)[gid];
    const float4 t = reinterpret_cast<const float4*>(target)[gid];

    float s = (softplus_f(p.x) - p.x * t.x)
            + (softplus_f(p.y) - p.y * t.y)
            + (softplus_f(p.z) - p.z * t.z)
            + (softplus_f(p.w) - p.w * t.w);

    float v = block_reduce_256(s, warp_sums);

    if (threadIdx.x == 0) {
        g_partials[blockIdx.x] = v;
        __threadfence();
        unsigned int prev = atomicAdd(&g_count, 1u);
        is_last = (prev == BLOCKS - 1);
    }
    __syncthreads();

    if (is_last) {
        // All writers have fenced + counted; partials are visible.
        const volatile float* parts = g_partials;
        float t2 = parts[threadIdx.x] + parts[threadIdx.x + THREADS];
        __syncthreads();   // reuse warp_sums safely
        float total = block_reduce_256(t2, warp_sums);
        if (threadIdx.x == 0) {
            out[0] = total * (6.0f / (float)N_ELEMS);
            g_count = 0;   // re-arm for graph replay
        }
    }
}

extern "C" void kernel_launch(void* const* d_in, const int* in_sizes, int n_in,
                              void* d_out, int out_size)
{
    const float* pred   = (const float*)d_in[0];
    const float* target = (const float*)d_in[1];
    float* out = (float*)d_out;

    bce_fused_kernel<<<BLOCKS, THREADS>>>(pred, target, out);
}

// round 3
// speedup vs baseline: 1.0731x; 1.0731x over previous
#include <cuda_runtime.h>
#include <math.h>

// BoundaryLoss collapses analytically:
//   dist_map = min(dist_to_zero_set, dist_to_nonzero_set) == 0 everywhere
//   => final_weight = 1 + THETA = 6 (constant)
//   => out = 6 * mean( softplus(pred) - pred*target ),  N = 524288
//
// One-wave fused kernel: 128 blocks x 256 threads, 4 float4-pairs per thread
// front-batched (MLP=8 LDG.128 in flight), threadfence last-block finish.

#define N_ELEMS   524288
#define N_VEC4    (N_ELEMS / 4)        // 131072
#define BLOCKS    128
#define THREADS   256
#define PER_TH    4                    // float4s per thread per array
#define STRIDE    (BLOCKS * THREADS)   // 32768; STRIDE*PER_TH == N_VEC4

__device__ float        g_partials[BLOCKS];
__device__ unsigned int g_count = 0;

__device__ __forceinline__ float softplus_f(float x) {
    // logaddexp(0, x) = max(x,0) + log1p(exp(-|x|))
    return fmaxf(x, 0.0f) + log1pf(__expf(-fabsf(x)));
}

__device__ __forceinline__ float bce4(const float4 p, const float4 t) {
    return (softplus_f(p.x) - p.x * t.x)
         + (softplus_f(p.y) - p.y * t.y)
         + (softplus_f(p.z) - p.z * t.z)
         + (softplus_f(p.w) - p.w * t.w);
}

__device__ __forceinline__ float block_reduce_256(float s, float* warp_sums) {
    #pragma unroll
    for (int off = 16; off > 0; off >>= 1)
        s += __shfl_down_sync(0xFFFFFFFFu, s, off);
    const int lane = threadIdx.x & 31;
    const int wid  = threadIdx.x >> 5;
    if (lane == 0) warp_sums[wid] = s;
    __syncthreads();
    float v = 0.0f;
    if (wid == 0) {
        v = (lane < THREADS / 32) ? warp_sums[lane] : 0.0f;
        #pragma unroll
        for (int off = 4; off > 0; off >>= 1)
            v += __shfl_down_sync(0xFFFFFFFFu, v, off);
    }
    return v;   // valid in lane 0 of warp 0
}

__global__ __launch_bounds__(THREADS) void bce_fused_kernel(
    const float* __restrict__ pred, const float* __restrict__ target,
    float* __restrict__ out)
{
    __shared__ float warp_sums[THREADS / 32];
    __shared__ bool  is_last;

    const int base = blockIdx.x * THREADS + threadIdx.x;
    const float4* __restrict__ p4 = reinterpret_cast<const float4*>(pred);
    const float4* __restrict__ t4 = reinterpret_cast<const float4*>(target);

    // Front-batch all 8 loads -> MLP=8, hides DRAM latency.
    float4 p[PER_TH], t[PER_TH];
    #pragma unroll
    for (int k = 0; k < PER_TH; k++) p[k] = p4[base + k * STRIDE];
    #pragma unroll
    for (int k = 0; k < PER_TH; k++) t[k] = t4[base + k * STRIDE];

    float s = 0.0f;
    #pragma unroll
    for (int k = 0; k < PER_TH; k++) s += bce4(p[k], t[k]);

    float v = block_reduce_256(s, warp_sums);

    if (threadIdx.x == 0) {
        g_partials[blockIdx.x] = v;
        __threadfence();
        unsigned int prev = atomicAdd(&g_count, 1u);
        is_last = (prev == BLOCKS - 1);
    }
    __syncthreads();

    if (is_last) {
        const volatile float* parts = g_partials;
        float t2 = (threadIdx.x < BLOCKS) ? parts[threadIdx.x] : 0.0f;
        __syncthreads();   // warp_sums reuse
        float total = block_reduce_256(t2, warp_sums);
        if (threadIdx.x == 0) {
            out[0] = total * (6.0f / (float)N_ELEMS);
            g_count = 0;   // re-arm for graph replay
        }
    }
}

extern "C" void kernel_launch(void* const* d_in, const int* in_sizes, int n_in,
                              void* d_out, int out_size)
{
    const float* pred   = (const float*)d_in[0];
    const float* target = (const float*)d_in[1];
    float* out = (float*)d_out;

    bce_fused_kernel<<<BLOCKS, THREADS>>>(pred, target, out);
}

// round 4
// speedup vs baseline: 1.1296x; 1.0526x over previous
#include <cuda_runtime.h>
#include <math.h>

// BoundaryLoss collapses analytically:
//   dist_map = min(dist_to_zero_set, dist_to_nonzero_set) == 0 everywhere
//   => final_weight = 1 + THETA = 6 (constant)
//   => out = 6 * mean( softplus(pred) - pred*target ),  N = 524288
//
// No grid-wide sync: each block atomicAdds its scaled partial into out[0].
// out[0] is zeroed by a cudaMemsetAsync graph node before the kernel.
// Blocks retire independently -> no fence / straggler tail.

#define N_ELEMS   524288
#define N_VEC4    (N_ELEMS / 4)        // 131072
#define BLOCKS    256
#define THREADS   256
#define PER_TH    2                    // float4s per thread per array
#define STRIDE    (BLOCKS * THREADS)   // 65536; STRIDE*PER_TH == N_VEC4

__device__ __forceinline__ float softplus_f(float x) {
    // logaddexp(0, x) = max(x,0) + log1p(exp(-|x|))
    return fmaxf(x, 0.0f) + log1pf(__expf(-fabsf(x)));
}

__device__ __forceinline__ float bce4(const float4 p, const float4 t) {
    return (softplus_f(p.x) - p.x * t.x)
         + (softplus_f(p.y) - p.y * t.y)
         + (softplus_f(p.z) - p.z * t.z)
         + (softplus_f(p.w) - p.w * t.w);
}

__global__ __launch_bounds__(THREADS) void bce_atomic_kernel(
    const float* __restrict__ pred, const float* __restrict__ target,
    float* __restrict__ out)
{
    __shared__ float warp_sums[THREADS / 32];

    const int base = blockIdx.x * THREADS + threadIdx.x;
    const float4* __restrict__ p4 = reinterpret_cast<const float4*>(pred);
    const float4* __restrict__ t4 = reinterpret_cast<const float4*>(target);

    // Front-batch 4 independent LDG.128 (MLP=4).
    float4 p[PER_TH], t[PER_TH];
    #pragma unroll
    for (int k = 0; k < PER_TH; k++) p[k] = p4[base + k * STRIDE];
    #pragma unroll
    for (int k = 0; k < PER_TH; k++) t[k] = t4[base + k * STRIDE];

    float s = 0.0f;
    #pragma unroll
    for (int k = 0; k < PER_TH; k++) s += bce4(p[k], t[k]);

    // warp reduce
    #pragma unroll
    for (int off = 16; off > 0; off >>= 1)
        s += __shfl_down_sync(0xFFFFFFFFu, s, off);

    const int lane = threadIdx.x & 31;
    const int wid  = threadIdx.x >> 5;
    if (lane == 0) warp_sums[wid] = s;
    __syncthreads();

    if (wid == 0) {
        float v = (lane < THREADS / 32) ? warp_sums[lane] : 0.0f;
        #pragma unroll
        for (int off = 4; off > 0; off >>= 1)
            v += __shfl_down_sync(0xFFFFFFFFu, v, off);
        if (lane == 0)
            atomicAdd(out, v * (6.0f / (float)N_ELEMS));
    }
}

extern "C" void kernel_launch(void* const* d_in, const int* in_sizes, int n_in,
                              void* d_out, int out_size)
{
    const float* pred   = (const float*)d_in[0];
    const float* target = (const float*)d_in[1];
    float* out = (float*)d_out;

    cudaMemsetAsync(out, 0, sizeof(float));
    bce_atomic_kernel<<<BLOCKS, THREADS>>>(pred, target, out);
}

// round 5
// speedup vs baseline: 1.2345x; 1.0929x over previous
#include <cuda_runtime.h>
#include <math.h>

// BoundaryLoss collapses analytically:
//   dist_map = min(dist_to_zero_set, dist_to_nonzero_set) == 0 everywhere
//   => final_weight = 1 + THETA = 6 (constant)
//   => out = 6 * mean( softplus(pred) - pred*target ),  N = 524288
//
// Max-occupancy streaming reduce: 512 blocks x 256 threads, one float4 pair
// per thread (131072 threads = N/4). Per-block atomicAdd into out[0]
// (zeroed by a cudaMemsetAsync graph node). No grid-wide sync, no tail.

#define N_ELEMS   524288
#define BLOCKS    512
#define THREADS   256        // BLOCKS*THREADS == N_ELEMS/4 exactly

__device__ __forceinline__ float softplus_f(float x) {
    // logaddexp(0, x) = max(x,0) + log(1 + exp(-|x|)); fast-math variants are
    // ~1e-7 accurate here, far inside the 1e-3 gate.
    return fmaxf(x, 0.0f) + __logf(1.0f + __expf(-fabsf(x)));
}

__global__ __launch_bounds__(THREADS) void bce_atomic_kernel(
    const float* __restrict__ pred, const float* __restrict__ target,
    float* __restrict__ out)
{
    __shared__ float warp_sums[THREADS / 32];

    const int gid = blockIdx.x * THREADS + threadIdx.x;

    const float4 p = reinterpret_cast<const float4*>(pred)[gid];
    const float4 t = reinterpret_cast<const float4*>(target)[gid];

    float s = (softplus_f(p.x) - p.x * t.x)
            + (softplus_f(p.y) - p.y * t.y)
            + (softplus_f(p.z) - p.z * t.z)
            + (softplus_f(p.w) - p.w * t.w);

    // warp reduce
    #pragma unroll
    for (int off = 16; off > 0; off >>= 1)
        s += __shfl_down_sync(0xFFFFFFFFu, s, off);

    const int lane = threadIdx.x & 31;
    const int wid  = threadIdx.x >> 5;
    if (lane == 0) warp_sums[wid] = s;
    __syncthreads();

    if (wid == 0) {
        float v = (lane < THREADS / 32) ? warp_sums[lane] : 0.0f;
        #pragma unroll
        for (int off = 4; off > 0; off >>= 1)
            v += __shfl_down_sync(0xFFFFFFFFu, v, off);
        if (lane == 0)
            atomicAdd(out, v * (6.0f / (float)N_ELEMS));   // RED, no return
    }
}

extern "C" void kernel_launch(void* const* d_in, const int* in_sizes, int n_in,
                              void* d_out, int out_size)
{
    const float* pred   = (const float*)d_in[0];
    const float* target = (const float*)d_in[1];
    float* out = (float*)d_out;

    cudaMemsetAsync(out, 0, sizeof(float));
    bce_atomic_kernel<<<BLOCKS, THREADS>>>(pred, target, out);
}

// round 6
// speedup vs baseline: 1.3223x; 1.0711x over previous
#include <cuda_runtime.h>
#include <math.h>

// BoundaryLoss collapses analytically:
//   dist_map = min(dist_to_zero_set, dist_to_nonzero_set) == 0 everywhere
//   => final_weight = 1 + THETA = 6 (constant)
//   => out = 6 * mean( softplus(pred) - pred*target ),  N = 524288
//
// Single-node graph: blocks atomicAdd partials into g_accum, then bump a
// counter. Ordering: each block does add -> threadfence -> count, so the
// block seeing prev==BLOCKS-1 knows ALL adds are globally visible. That
// block atomicExch's the accumulator (read total + re-arm to 0 for the next
// graph replay in one atomic), scales, and writes out[0]. No memset node.

#define N_ELEMS   524288
#define BLOCKS    512
#define THREADS   256        // BLOCKS*THREADS == N_ELEMS/4 exactly

__device__ float        g_accum = 0.0f;
__device__ unsigned int g_count = 0;

__device__ __forceinline__ float softplus_f(float x) {
    // logaddexp(0, x) = max(x,0) + log(1 + exp(-|x|)); ~1e-7 accurate.
    return fmaxf(x, 0.0f) + __logf(1.0f + __expf(-fabsf(x)));
}

__global__ __launch_bounds__(THREADS) void bce_atomic_kernel(
    const float* __restrict__ pred, const float* __restrict__ target,
    float* __restrict__ out)
{
    __shared__ float warp_sums[THREADS / 32];

    const int gid = blockIdx.x * THREADS + threadIdx.x;

    const float4 p = reinterpret_cast<const float4*>(pred)[gid];
    const float4 t = reinterpret_cast<const float4*>(target)[gid];

    float s = (softplus_f(p.x) - p.x * t.x)
            + (softplus_f(p.y) - p.y * t.y)
            + (softplus_f(p.z) - p.z * t.z)
            + (softplus_f(p.w) - p.w * t.w);

    // warp reduce
    #pragma unroll
    for (int off = 16; off > 0; off >>= 1)
        s += __shfl_down_sync(0xFFFFFFFFu, s, off);

    const int lane = threadIdx.x & 31;
    const int wid  = threadIdx.x >> 5;
    if (lane == 0) warp_sums[wid] = s;
    __syncthreads();

    if (wid == 0) {
        float v = (lane < THREADS / 32) ? warp_sums[lane] : 0.0f;
        #pragma unroll
        for (int off = 4; off > 0; off >>= 1)
            v += __shfl_down_sync(0xFFFFFFFFu, v, off);

        if (lane == 0) {
            atomicAdd(&g_accum, v);
            __threadfence();
            unsigned int prev = atomicAdd(&g_count, 1u);
            if (prev == BLOCKS - 1) {
                // All 512 adds are globally visible. Read total and re-arm
                // the accumulator atomically for the next graph replay.
                float total = atomicExch(&g_accum, 0.0f);
                out[0] = total * (6.0f / (float)N_ELEMS);
                g_count = 0;
            }
        }
    }
}

extern "C" void kernel_launch(void* const* d_in, const int* in_sizes, int n_in,
                              void* d_out, int out_size)
{
    const float* pred   = (const float*)d_in[0];
    const float* target = (const float*)d_in[1];
    float* out = (float*)d_out;

    bce_atomic_kernel<<<BLOCKS, THREADS>>>(pred, target, out);
}

// round 7
// speedup vs baseline: 1.3349x; 1.0096x over previous
#include <cuda_runtime.h>
#include <math.h>

// BoundaryLoss collapses analytically:
//   dist_map = min(dist_to_zero_set, dist_to_nonzero_set) == 0 everywhere
//   => final_weight = 1 + THETA = 6 (constant)
//   => out = 6 * mean( softplus(pred) - pred*target ),  N = 524288
//
// Kernel is MUFU-bound (2 MUFU/elt: EX2 + LG2 = 1.05M ops @ 74/cyc chip).
// Log-fusion: sum_i log(1+e^-|xi|) = log(prod_i (1+e^-|xi|)).
//   - per-thread product over its 4 elements (<= 2^4)
//   - pair-fuse across lanes with one shfl (<= 2^8, fp32-safe)
// => MUFU/elt drops 2.0 -> 1.125 (1 exp + 1/8 log).
//
// Single-node graph: per-block atomicAdd into g_accum + counter; the last
// counted block atomicExch's the total (re-arming to 0 for the next replay).

#define N_ELEMS   524288
#define BLOCKS    512
#define THREADS   256        // BLOCKS*THREADS == N_ELEMS/4 exactly

__device__ float        g_accum = 0.0f;
__device__ unsigned int g_count = 0;

__global__ __launch_bounds__(THREADS) void bce_atomic_kernel(
    const float* __restrict__ pred, const float* __restrict__ target,
    float* __restrict__ out)
{
    __shared__ float warp_sums[THREADS / 32];

    const int gid = blockIdx.x * THREADS + threadIdx.x;

    const float4 p = reinterpret_cast<const float4*>(pred)[gid];
    const float4 t = reinterpret_cast<const float4*>(target)[gid];

    // Linear part: max(x,0) - x*t  (fma/alu pipes, cheap)
    float lin = (fmaxf(p.x, 0.0f) - p.x * t.x)
              + (fmaxf(p.y, 0.0f) - p.y * t.y)
              + (fmaxf(p.z, 0.0f) - p.z * t.z)
              + (fmaxf(p.w, 0.0f) - p.w * t.w);

    // Transcendental part: product of (1 + e^-|x|) over this thread's 4 elts.
    float e0 = __expf(-fabsf(p.x));
    float e1 = __expf(-fabsf(p.y));
    float e2 = __expf(-fabsf(p.z));
    float e3 = __expf(-fabsf(p.w));
    float pr = ((1.0f + e0) * (1.0f + e1)) * ((1.0f + e2) * (1.0f + e3)); // in [1,16]

    // Pair-fuse: lane even also takes lane odd's product (<= 2^8), does ONE log
    // covering 8 elements; odd lanes contribute 0. Sum over the warp is exact
    // up to reassociation.
    float pr_nb = __shfl_down_sync(0xFFFFFFFFu, pr, 1);
    float s = lin;
    if ((threadIdx.x & 1) == 0)
        s += __logf(pr * pr_nb);

    // warp reduce
    #pragma unroll
    for (int off = 16; off > 0; off >>= 1)
        s += __shfl_down_sync(0xFFFFFFFFu, s, off);

    const int lane = threadIdx.x & 31;
    const int wid  = threadIdx.x >> 5;
    if (lane == 0) warp_sums[wid] = s;
    __syncthreads();

    if (wid == 0) {
        float v = (lane < THREADS / 32) ? warp_sums[lane] : 0.0f;
        #pragma unroll
        for (int off = 4; off > 0; off >>= 1)
            v += __shfl_down_sync(0xFFFFFFFFu, v, off);

        if (lane == 0) {
            atomicAdd(&g_accum, v);
            __threadfence();
            unsigned int prev = atomicAdd(&g_count, 1u);
            if (prev == BLOCKS - 1) {
                // All adds globally visible; read total and re-arm in one op.
                float total = atomicExch(&g_accum, 0.0f);
                out[0] = total * (6.0f / (float)N_ELEMS);
                g_count = 0;
            }
        }
    }
}

extern "C" void kernel_launch(void* const* d_in, const int* in_sizes, int n_in,
                              void* d_out, int out_size)
{
    const float* pred   = (const float*)d_in[0];
    const float* target = (const float*)d_in[1];
    float* out = (float*)d_out;

    bce_atomic_kernel<<<BLOCKS, THREADS>>>(pred, target, out);
}

// round 8
// speedup vs baseline: 1.3478x; 1.0097x over previous
#include <cuda_runtime.h>
#include <math.h>

// BoundaryLoss collapses analytically:
//   dist_map = min(dist_to_zero_set, dist_to_nonzero_set) == 0 everywhere
//   => final_weight = 1 + THETA = 6 (constant)
//   => out = 6 * mean( softplus(pred) - pred*target ),  N = 524288
//
// Fence-free single-node finish: each block does ONE atomicAdd(double) of
// (partial + 2^32). Low part accumulates the sum; 2^32 multiples count block
// arrivals — in the same atomic word, so the block seeing old >= 511*2^32 is
// provably last WITHOUT any __threadfence (R6/R7's 512 GPU-scope membars cost
// ~1.9us). bce >= 0 so partials are positive; counts <= 2^41 keep double
// ulp at 2^-11 (rel err ~1e-9). Last block writes out[0] and atomicExch's the
// accumulator to 0, re-arming for the next graph replay.

#define N_ELEMS   524288
#define BLOCKS    512
#define THREADS   256        // BLOCKS*THREADS == N_ELEMS/4 exactly

#define TAG       4294967296.0                    // 2^32 per-block arrival tag
#define LAST_THR  (511.0 * 4294967296.0)
#define FULL_TAG  (512.0 * 4294967296.0)

__device__ double g_accum = 0.0;

__global__ __launch_bounds__(THREADS) void bce_atomic_kernel(
    const float* __restrict__ pred, const float* __restrict__ target,
    float* __restrict__ out)
{
    __shared__ float warp_sums[THREADS / 32];

    const int gid = blockIdx.x * THREADS + threadIdx.x;

    const float4 p = reinterpret_cast<const float4*>(pred)[gid];
    const float4 t = reinterpret_cast<const float4*>(target)[gid];

    // Linear part: max(x,0) - x*t
    float lin = (fmaxf(p.x, 0.0f) - p.x * t.x)
              + (fmaxf(p.y, 0.0f) - p.y * t.y)
              + (fmaxf(p.z, 0.0f) - p.z * t.z)
              + (fmaxf(p.w, 0.0f) - p.w * t.w);

    // Transcendental part with log-fusion:
    // sum log(1+e^-|x|) = log(prod (1+e^-|x|)); per-thread product <= 2^4,
    // pair-fused across lanes <= 2^8 (fp32-safe).
    float e0 = __expf(-fabsf(p.x));
    float e1 = __expf(-fabsf(p.y));
    float e2 = __expf(-fabsf(p.z));
    float e3 = __expf(-fabsf(p.w));
    float pr = ((1.0f + e0) * (1.0f + e1)) * ((1.0f + e2) * (1.0f + e3));

    float pr_nb = __shfl_down_sync(0xFFFFFFFFu, pr, 1);
    float s = lin;
    if ((threadIdx.x & 1) == 0)
        s += __logf(pr * pr_nb);

    // warp reduce
    #pragma unroll
    for (int off = 16; off > 0; off >>= 1)
        s += __shfl_down_sync(0xFFFFFFFFu, s, off);

    const int lane = threadIdx.x & 31;
    const int wid  = threadIdx.x >> 5;
    if (lane == 0) warp_sums[wid] = s;
    __syncthreads();

    if (wid == 0) {
        float v = (lane < THREADS / 32) ? warp_sums[lane] : 0.0f;
        #pragma unroll
        for (int off = 4; off > 0; off >>= 1)
            v += __shfl_down_sync(0xFFFFFFFFu, v, off);

        if (lane == 0) {
            double contrib = (double)v + TAG;
            double old = atomicAdd(&g_accum, contrib);
            if (old >= LAST_THR) {
                // Provably last: all 512 partials are in this very word.
                double total = (old + contrib) - FULL_TAG;
                out[0] = (float)(total * (6.0 / (double)N_ELEMS));
                atomicExch((unsigned long long*)&g_accum, 0ULL);  // re-arm
            }
        }
    }
}

extern "C" void kernel_launch(void* const* d_in, const int* in_sizes, int n_in,
                              void* d_out, int out_size)
{
    const float* pred   = (const float*)d_in[0];
    const float* target = (const float*)d_in[1];
    float* out = (float*)d_out;

    bce_atomic_kernel<<<BLOCKS, THREADS>>>(pred, target, out);
}